// round 1
// baseline (speedup 1.0000x reference)
#include <cuda_runtime.h>
#include <math.h>

// Problem constants
// B=8, C=512, H=W=32 -> N=1024 tokens, 8 heads, d_k=64, inner=512
#define NB   8
#define NC   512
#define NN   1024
#define NH   8
#define DK   64
#define ITOT 1536          // q (512) + kv (1024) projection rows
#define SCALE 0.125f       // 64^-0.5

// Scratch (device globals; allocation-free rule)
static __device__ float g_q[(size_t)NB * NH * NN * DK];   // [B,H,N,64]
static __device__ float g_k[(size_t)NB * NH * NN * DK];
static __device__ float g_v[(size_t)NB * NH * NN * DK];
static __device__ float g_mid[(size_t)NB * NN * 512];     // attention out, [B,N,H*64]

// ---------------------------------------------------------------------------
// Kernel 1: fused transpose + QKV projection.
// out[n, i] = sum_c x[b, c, n] * W[i, c] + bias[i]
// x viewed as A[C,N] row-major per batch (so A^T @ W^T without materializing xt).
// Scatter into head-major q/k/v buffers.
// Tile 64(n) x 64(i), k-step 16, 256 threads, 4x4 micro-tile.
// ---------------------------------------------------------------------------
__global__ __launch_bounds__(256) void qkv_gemm(
    const float* __restrict__ x, const float* __restrict__ Wq,
    const float* __restrict__ bq, const float* __restrict__ Wkv,
    const float* __restrict__ bkv)
{
    __shared__ float As[16][68];   // [cc][nn]  (reduction-major)
    __shared__ float Ws[16][68];   // [cc][ii]

    const int b  = blockIdx.z;
    const int n0 = blockIdx.x * 64;
    const int i0 = blockIdx.y * 64;      // 0..1535, tile never straddles 512

    const float* W;  const float* bias;  int ir0;
    if (i0 < 512) { W = Wq;  bias = bq;  ir0 = i0; }
    else          { W = Wkv; bias = bkv; ir0 = i0 - 512; }

    const int tid = threadIdx.x;
    const int tx  = tid & 15;   // i-dim micro (fast, 4 consecutive i)
    const int ty  = tid >> 4;   // n-dim micro

    const float* xb = x + (size_t)b * NC * NN;

    float acc[4][4];
#pragma unroll
    for (int un = 0; un < 4; un++)
#pragma unroll
        for (int ui = 0; ui < 4; ui++) acc[un][ui] = 0.f;

    const int lac = tid >> 4, lan = tid & 15;  // A load: row=lac, col4=lan
    const int lwi = tid >> 2, lwc = tid & 3;   // W load: row=lwi, col4=lwc

    for (int c0 = 0; c0 < NC; c0 += 16) {
        float4 av = *(const float4*)(xb + (size_t)(c0 + lac) * NN + n0 + lan * 4);
        float4 wv = *(const float4*)(W + (size_t)(ir0 + lwi) * NC + c0 + lwc * 4);
        __syncthreads();
        *(float4*)&As[lac][lan * 4] = av;
        Ws[lwc * 4 + 0][lwi] = wv.x;
        Ws[lwc * 4 + 1][lwi] = wv.y;
        Ws[lwc * 4 + 2][lwi] = wv.z;
        Ws[lwc * 4 + 3][lwi] = wv.w;
        __syncthreads();
#pragma unroll
        for (int cc = 0; cc < 16; cc++) {
            float4 a4 = *(const float4*)&As[cc][ty * 4];
            float4 w4 = *(const float4*)&Ws[cc][tx * 4];
            float aa[4] = {a4.x, a4.y, a4.z, a4.w};
            float ww[4] = {w4.x, w4.y, w4.z, w4.w};
#pragma unroll
            for (int un = 0; un < 4; un++)
#pragma unroll
                for (int ui = 0; ui < 4; ui++)
                    acc[un][ui] += aa[un] * ww[ui];
        }
    }

    // Epilogue: 4 consecutive i (same head, same q/k/v) -> float4 stores
    const int ig0 = i0 + tx * 4;
    float bs[4];
#pragma unroll
    for (int ui = 0; ui < 4; ui++) bs[ui] = bias[ir0 + tx * 4 + ui];

    float* dbase;
    int hh, dd;
    if (ig0 < 512) { dbase = g_q; hh = ig0 >> 6; dd = ig0 & 63; }
    else {
        int j0 = ig0 - 512;
        dbase = (j0 < 512) ? g_k : g_v;
        int jj = j0 & 511; hh = jj >> 6; dd = jj & 63;
    }
#pragma unroll
    for (int un = 0; un < 4; un++) {
        int n = n0 + ty * 4 + un;
        float4 ov = make_float4(acc[un][0] + bs[0], acc[un][1] + bs[1],
                                acc[un][2] + bs[2], acc[un][3] + bs[3]);
        *(float4*)(dbase + ((((size_t)b * NH + hh) * NN + n) * DK + dd)) = ov;
    }
}

// ---------------------------------------------------------------------------
// Kernel 2: attention, flash-style online softmax.
// One thread = one query row (q + O accumulator in registers).
// K/V tiles of 32 rows in smem (broadcast LDS.128 -> 4 FMAs per load).
// Scores staged in padded smem [128][33] (conflict-free).
// grid: (N/128, B*H), block 128.
// ---------------------------------------------------------------------------
__global__ __launch_bounds__(128) void attn_kernel()
{
    __shared__ float Ks[32][64];
    __shared__ float Vs[32][64];
    __shared__ float Ss[128][33];

    const int bh  = blockIdx.y;          // 0..63
    const int tid = threadIdx.x;
    const int r   = blockIdx.x * 128 + tid;

    const float* qrow = g_q + ((size_t)bh * NN + r) * DK;
    float q[DK];
#pragma unroll
    for (int d4 = 0; d4 < 16; d4++) {
        float4 t = *(const float4*)&qrow[d4 * 4];
        q[d4 * 4 + 0] = t.x; q[d4 * 4 + 1] = t.y;
        q[d4 * 4 + 2] = t.z; q[d4 * 4 + 3] = t.w;
    }

    float o[DK];
#pragma unroll
    for (int d = 0; d < DK; d++) o[d] = 0.f;
    float m = -1e30f, l = 0.f;

    const float4* kb4 = (const float4*)(g_k + (size_t)bh * NN * DK);
    const float4* vb4 = (const float4*)(g_v + (size_t)bh * NN * DK);

    for (int jt = 0; jt < NN / 32; jt++) {
        // cooperative tile load: 512 float4 per tile, 4 per thread
        int base4 = jt * 32 * 16;   // float4 index of tile start
#pragma unroll
        for (int u = 0; u < 4; u++) {
            int idx = tid + u * 128;
            ((float4*)Ks)[idx] = kb4[base4 + idx];
            ((float4*)Vs)[idx] = vb4[base4 + idx];
        }
        __syncthreads();

        // pass 1: scores + tile max
        float tmax = -1e30f;
#pragma unroll
        for (int j = 0; j < 32; j++) {
            float a0 = 0.f, a1 = 0.f, a2 = 0.f, a3 = 0.f;
#pragma unroll
            for (int d4 = 0; d4 < 16; d4++) {
                float4 kv = *(const float4*)&Ks[j][d4 * 4];
                a0 += q[d4 * 4 + 0] * kv.x;
                a1 += q[d4 * 4 + 1] * kv.y;
                a2 += q[d4 * 4 + 2] * kv.z;
                a3 += q[d4 * 4 + 3] * kv.w;
            }
            float sv = ((a0 + a1) + (a2 + a3)) * SCALE;
            Ss[tid][j] = sv;
            tmax = fmaxf(tmax, sv);
        }

        float mnew = fmaxf(m, tmax);
        float corr = __expf(m - mnew);
        l *= corr;
#pragma unroll
        for (int d = 0; d < DK; d++) o[d] *= corr;

        // pass 2: exp + accumulate O
#pragma unroll
        for (int j = 0; j < 32; j++) {
            float p = __expf(Ss[tid][j] - mnew);
            l += p;
#pragma unroll
            for (int d4 = 0; d4 < 16; d4++) {
                float4 vv = *(const float4*)&Vs[j][d4 * 4];
                o[d4 * 4 + 0] += p * vv.x;
                o[d4 * 4 + 1] += p * vv.y;
                o[d4 * 4 + 2] += p * vv.z;
                o[d4 * 4 + 3] += p * vv.w;
            }
        }
        m = mnew;
        __syncthreads();
    }

    const float inv = 1.f / l;
    const int b = bh >> 3, h = bh & 7;
    float* dst = g_mid + ((size_t)b * NN + r) * 512 + h * DK;
#pragma unroll
    for (int d4 = 0; d4 < 16; d4++) {
        float4 t = make_float4(o[d4 * 4 + 0] * inv, o[d4 * 4 + 1] * inv,
                               o[d4 * 4 + 2] * inv, o[d4 * 4 + 3] * inv);
        *(float4*)&dst[d4 * 4] = t;
    }
}

// ---------------------------------------------------------------------------
// Kernel 3: output projection. out[b,n,c] = sum_i mid[b,n,i]*Wp[c,i] + bp[c]
// Final reshape in reference is a raw flatten of [B,N,C], so write directly.
// ---------------------------------------------------------------------------
__global__ __launch_bounds__(256) void out_gemm(
    const float* __restrict__ Wp, const float* __restrict__ bp,
    float* __restrict__ out)
{
    __shared__ float As[16][68];   // [ii][nn]
    __shared__ float Ws[16][68];   // [ii][cc]

    const int b  = blockIdx.z;
    const int n0 = blockIdx.x * 64;
    const int c0 = blockIdx.y * 64;
    const int tid = threadIdx.x;
    const int tx = tid & 15;   // c micro (fast)
    const int ty = tid >> 4;   // n micro

    const float* mb = g_mid + (size_t)b * NN * 512;

    float acc[4][4];
#pragma unroll
    for (int un = 0; un < 4; un++)
#pragma unroll
        for (int ui = 0; ui < 4; ui++) acc[un][ui] = 0.f;

    const int lrow = tid >> 2, lic = tid & 3;

    for (int i0 = 0; i0 < 512; i0 += 16) {
        float4 av = *(const float4*)(mb + (size_t)(n0 + lrow) * 512 + i0 + lic * 4);
        float4 wv = *(const float4*)(Wp + (size_t)(c0 + lrow) * 512 + i0 + lic * 4);
        __syncthreads();
        As[lic * 4 + 0][lrow] = av.x;
        As[lic * 4 + 1][lrow] = av.y;
        As[lic * 4 + 2][lrow] = av.z;
        As[lic * 4 + 3][lrow] = av.w;
        Ws[lic * 4 + 0][lrow] = wv.x;
        Ws[lic * 4 + 1][lrow] = wv.y;
        Ws[lic * 4 + 2][lrow] = wv.z;
        Ws[lic * 4 + 3][lrow] = wv.w;
        __syncthreads();
#pragma unroll
        for (int cc = 0; cc < 16; cc++) {
            float4 a4 = *(const float4*)&As[cc][ty * 4];
            float4 w4 = *(const float4*)&Ws[cc][tx * 4];
            float aa[4] = {a4.x, a4.y, a4.z, a4.w};
            float ww[4] = {w4.x, w4.y, w4.z, w4.w};
#pragma unroll
            for (int un = 0; un < 4; un++)
#pragma unroll
                for (int ui = 0; ui < 4; ui++)
                    acc[un][ui] += aa[un] * ww[ui];
        }
    }

    float bs[4];
#pragma unroll
    for (int ui = 0; ui < 4; ui++) bs[ui] = bp[c0 + tx * 4 + ui];
#pragma unroll
    for (int un = 0; un < 4; un++) {
        int n = n0 + ty * 4 + un;
        float4 ov = make_float4(acc[un][0] + bs[0], acc[un][1] + bs[1],
                                acc[un][2] + bs[2], acc[un][3] + bs[3]);
        *(float4*)(out + ((size_t)b * NN + n) * 512 + c0 + tx * 4) = ov;
    }
}

// ---------------------------------------------------------------------------
// Inputs (metadata order): x, y, Wq, bq, Wkv, bkv, Wp, bp.  y unused (ref
// only shape-checks it). Output dtype float32, layout = raw [B,N,C] flatten.
// ---------------------------------------------------------------------------
extern "C" void kernel_launch(void* const* d_in, const int* in_sizes, int n_in,
                              void* d_out, int out_size)
{
    const float* x   = (const float*)d_in[0];
    const float* Wq  = (const float*)d_in[2];
    const float* bq  = (const float*)d_in[3];
    const float* Wkv = (const float*)d_in[4];
    const float* bkv = (const float*)d_in[5];
    const float* Wp  = (const float*)d_in[6];
    const float* bp  = (const float*)d_in[7];
    float* out = (float*)d_out;

    qkv_gemm<<<dim3(NN / 64, ITOT / 64, NB), 256>>>(x, Wq, bq, Wkv, bkv);
    attn_kernel<<<dim3(NN / 128, NB * NH), 128>>>();
    out_gemm<<<dim3(NN / 64, 512 / 64, NB), 256>>>(Wp, bp, out);
}